// round 3
// baseline (speedup 1.0000x reference)
#include <cuda_runtime.h>
#include <cstdint>

// Problem shape: B=256, S=128, D=32, K=8192  ->  N = 32768 points
#define DIMS      32
#define NPTS_MAX  32768
#define KMAX      8192
#define KSPLIT    4                 // K-slices (grid.y)
#define BLOCK     224               // threads per CTA = points per CTA
#define NPB       148               // point blocks: 148*4 = 592 CTAs = 2 full waves @ occ 2
#define TILE      256               // centers per smem tile

// Scratch (allocation-free rule: __device__ globals)
__device__ float g_c2[KMAX];
__device__ float g_part_s[KSPLIT][NPTS_MAX];
__device__ int   g_part_i[KSPLIT][NPTS_MAX];

// ---- init partials to sentinel (diagnosable if label_kernel never runs) ----
__global__ void init_kernel(int N) {
    int n = blockIdx.x * blockDim.x + threadIdx.x;
    if (n < N) {
#pragma unroll
        for (int s = 0; s < KSPLIT; s++) {
            g_part_s[s][n] = 3.402823466e38f;
            g_part_i[s][n] = 12345;      // sentinel label
        }
    }
}

// ---- precompute ||c_k||^2 (sequential order d=0..31, matches ref-style reduce) ----
__global__ void c2_kernel(const float* __restrict__ c, int K) {
    int k = blockIdx.x * blockDim.x + threadIdx.x;
    if (k < K) {
        const float* row = c + (size_t)k * DIMS;
        float s = 0.0f;
#pragma unroll
        for (int i = 0; i < DIMS; i++) s = fmaf(row[i], row[i], s);
        g_c2[k] = s;
    }
}

// ---- main: each CTA = 224 points x 2048 centers ----
__global__ __launch_bounds__(BLOCK, 2)
void label_kernel(const float* __restrict__ x, const float* __restrict__ c,
                  int N, int K) {
    __shared__ __align__(16) float sc[TILE * DIMS]; // 32 KB center tile
    __shared__ float sh[TILE];                      // ||c||^2 tile

    const int tid   = threadIdx.x;
    const int ks    = blockIdx.y;
    const int KS    = K / KSPLIT;                   // 2048
    const int kbase = ks * KS;

    const int idx = blockIdx.x * BLOCK + tid;
    const bool valid = (idx < N);
    float px[DIMS];
    if (valid) {
        const float4* row = reinterpret_cast<const float4*>(x + (size_t)idx * DIMS);
#pragma unroll
        for (int i = 0; i < DIMS / 4; i++) {
            float4 v = row[i];
            px[4 * i + 0] = v.x; px[4 * i + 1] = v.y;
            px[4 * i + 2] = v.z; px[4 * i + 3] = v.w;
        }
    } else {
#pragma unroll
        for (int i = 0; i < DIMS; i++) px[i] = 0.0f;
    }
    float x2 = 0.0f;
#pragma unroll
    for (int i = 0; i < DIMS; i++) x2 = fmaf(px[i], px[i], x2);

    float best = 3.402823466e38f;
    int   bk   = 0;
    bool  any  = false;

    const int ntiles = KS / TILE;                   // 8
    for (int t = 0; t < ntiles; t++) {
        __syncthreads();
        const float4* src = reinterpret_cast<const float4*>(c + (size_t)(kbase + t * TILE) * DIMS);
        float4* dst = reinterpret_cast<float4*>(sc);
        for (int i = tid; i < TILE * DIMS / 4; i += BLOCK) dst[i] = src[i];
        for (int i = tid; i < TILE; i += BLOCK) sh[i] = g_c2[kbase + t * TILE + i];
        __syncthreads();

        const int kg0 = kbase + t * TILE;
        // 2 centers per step: two independent FMA chains (ILP 2 saturates fma pipe),
        // each chain strictly in d=0..31 order to track the reference's rounding.
        for (int kk = 0; kk < TILE; kk += 2) {
            const float4* r0 = reinterpret_cast<const float4*>(sc + kk * DIMS);
            const float4* r1 = reinterpret_cast<const float4*>(sc + (kk + 1) * DIMS);
            float xc0 = 0.0f, xc1 = 0.0f;
#pragma unroll
            for (int d4 = 0; d4 < DIMS / 4; d4++) {
                float4 a = r0[d4];
                float4 b = r1[d4];
                xc0 = fmaf(px[4 * d4 + 0], a.x, xc0);
                xc1 = fmaf(px[4 * d4 + 0], b.x, xc1);
                xc0 = fmaf(px[4 * d4 + 1], a.y, xc0);
                xc1 = fmaf(px[4 * d4 + 1], b.y, xc1);
                xc0 = fmaf(px[4 * d4 + 2], a.z, xc0);
                xc1 = fmaf(px[4 * d4 + 2], b.z, xc1);
                xc0 = fmaf(px[4 * d4 + 3], a.w, xc0);
                xc1 = fmaf(px[4 * d4 + 3], b.w, xc1);
            }
            // (x2 - 2*xc) + c2 : 2*xc exact, fmaf(-2,xc,x2) == round(x2-2xc)
            float d20 = fmaf(-2.0f, xc0, x2) + sh[kk];
            float d21 = fmaf(-2.0f, xc1, x2) + sh[kk + 1];
            if (d20 < best) { best = d20; bk = kg0 + kk;     any = true; }
            if (d21 < best) { best = d21; bk = kg0 + kk + 1; any = true; }
        }
    }

    if (valid && any) {
        g_part_s[ks][idx] = best;
        g_part_i[ks][idx] = bk;
    }
}

// ---- merge K-split partials; OUTPUT AS FLOAT32 ----
__global__ void combine_kernel(float* __restrict__ out, int N) {
    int n = blockIdx.x * blockDim.x + threadIdx.x;
    if (n < N) {
        float b  = g_part_s[0][n];
        int   bi = g_part_i[0][n];
#pragma unroll
        for (int s = 1; s < KSPLIT; s++) {
            float v = g_part_s[s][n];
            if (v < b) { b = v; bi = g_part_i[s][n]; }   // strict <: ascending slice order keeps first-min
        }
        out[n] = (float)bi;    // labels 0..8191 exact in fp32
    }
}

extern "C" void kernel_launch(void* const* d_in, const int* in_sizes, int n_in,
                              void* d_out, int out_size) {
    // Assign inputs BY SIZE (robust to metadata ordering):
    // inpt = 256*128*32 = 1048576 elems, centers = 8192*32 = 262144 elems.
    const float* x;
    const float* c;
    int nx_elems, nc_elems;
    if (in_sizes[0] >= in_sizes[1]) {
        x = (const float*)d_in[0]; nx_elems = in_sizes[0];
        c = (const float*)d_in[1]; nc_elems = in_sizes[1];
    } else {
        x = (const float*)d_in[1]; nx_elems = in_sizes[1];
        c = (const float*)d_in[0]; nc_elems = in_sizes[0];
    }
    float* out = (float*)d_out;   // labels written as float32

    int N = nx_elems / DIMS;      // 32768
    int K = nc_elems / DIMS;      // 8192

    init_kernel<<<(N + 255) / 256, 256>>>(N);
    c2_kernel<<<(K + 127) / 128, 128>>>(c, K);

    dim3 grid(NPB, KSPLIT);       // 148 x 4 = 592 CTAs
    label_kernel<<<grid, BLOCK>>>(x, c, N, K);

    combine_kernel<<<(N + 255) / 256, 256>>>(out, N);
}

// round 5
// speedup vs baseline: 1.8399x; 1.8399x over previous
#include <cuda_runtime.h>
#include <cuda_bf16.h>
#include <cstdint>
#include <cstring>

// Problem: N=32768 points, K=8192 centers, D=32. fp32 in, labels-as-fp32 out.
#define DIMS      32
#define NPOINTS   32768
#define KCENT     8192
#define KSTEPS    12            // 192 expanded K / 16 per mma
#define ROWB      384           // bytes per expanded row (192 bf16)
#define ROWW      96            // words per expanded row
#define PITCH     400           // smem row pitch (conflict-free ldmatrix: 400/16=25, 25%8=1)
#define TILE_N    128           // centers per smem tile
#define NTILES    (KCENT / TILE_N)   // 64
#define THREADS   448           // 14 warps x 16 points = 224 points/CTA
#define GRID      148           // one CTA per SM, single wave
#define NPAD      (GRID * 224)  // 33152 rows in expanded A (pad reads zeros)

// smem layout (dynamic): B tiles double-buffered + c2 tiles
#define SM_B(s)   ((s) * (TILE_N * PITCH))          // 0 / 51200
#define SM_C2(s)  (102400 + (s) * 512)
#define SMEM_TOTAL 103424

// ---- pre-expanded operands (allocation-free: __device__ globals, zero-initialized) ----
__device__ __align__(16) uint8_t g_aexp[(size_t)NPAD * ROWB];     // ~12.7 MB
__device__ __align__(16) uint8_t g_bexp[(size_t)KCENT * ROWB];    // 3.1 MB
__device__ float g_c2[KCENT];

// ---- split fp32 into 3 bf16 limbs (values returned as exact floats) ----
__device__ __forceinline__ void split3(float v, float& f0, float& f1, float& f2) {
    f0 = __bfloat162float(__float2bfloat16(v));
    float r1 = v - f0;
    f1 = __bfloat162float(__float2bfloat16(r1));
    float r2 = r1 - f1;
    f2 = __bfloat162float(__float2bfloat16(r2));
}
__device__ __forceinline__ uint32_t pack_bf2(float lo, float hi) {
    __nv_bfloat162 h = __floats2bfloat162_rn(lo, hi);
    uint32_t u; memcpy(&u, &h, 4); return u;
}

// ---- prep: expand points (negated? no — plain x; score = c2 - 2 x.c) ----
__global__ void prep_points(const float* __restrict__ x, int N) {
    int p = blockIdx.x * blockDim.x + threadIdx.x;
    if (p >= N) return;
    float s0[DIMS], s1[DIMS], s2[DIMS];
    const float4* row = reinterpret_cast<const float4*>(x + (size_t)p * DIMS);
#pragma unroll
    for (int q = 0; q < DIMS / 4; q++) {
        float4 v = row[q];
        split3(v.x, s0[4*q+0], s1[4*q+0], s2[4*q+0]);
        split3(v.y, s0[4*q+1], s1[4*q+1], s2[4*q+1]);
        split3(v.z, s0[4*q+2], s1[4*q+2], s2[4*q+2]);
        split3(v.w, s0[4*q+3], s1[4*q+3], s2[4*q+3]);
    }
    uint32_t w[ROWW];
    const float* segs[6] = { s0, s0, s1, s1, s0, s2 };   // A: [a0,a0,a1,a1,a0,a2]
#pragma unroll
    for (int s = 0; s < 6; s++)
#pragma unroll
        for (int d = 0; d < 16; d++)
            w[s * 16 + d] = pack_bf2(segs[s][2*d], segs[s][2*d+1]);
    uint4* dst = reinterpret_cast<uint4*>(g_aexp + (size_t)p * ROWB);
#pragma unroll
    for (int i = 0; i < ROWW / 4; i++)
        dst[i] = make_uint4(w[4*i], w[4*i+1], w[4*i+2], w[4*i+3]);
}

// ---- prep: expand centers + ||c||^2 ----
__global__ void prep_centers(const float* __restrict__ c, int K) {
    int k = blockIdx.x * blockDim.x + threadIdx.x;
    if (k >= K) return;
    float s0[DIMS], s1[DIMS], s2[DIMS];
    float c2 = 0.0f;
    const float4* row = reinterpret_cast<const float4*>(c + (size_t)k * DIMS);
#pragma unroll
    for (int q = 0; q < DIMS / 4; q++) {
        float4 v = row[q];
        split3(v.x, s0[4*q+0], s1[4*q+0], s2[4*q+0]);
        split3(v.y, s0[4*q+1], s1[4*q+1], s2[4*q+1]);
        split3(v.z, s0[4*q+2], s1[4*q+2], s2[4*q+2]);
        split3(v.w, s0[4*q+3], s1[4*q+3], s2[4*q+3]);
        c2 = fmaf(v.x, v.x, c2); c2 = fmaf(v.y, v.y, c2);
        c2 = fmaf(v.z, v.z, c2); c2 = fmaf(v.w, v.w, c2);
    }
    uint32_t w[ROWW];
    const float* segs[6] = { s0, s1, s0, s1, s2, s0 };   // B: [b0,b1,b0,b1,b2,b0]
#pragma unroll
    for (int s = 0; s < 6; s++)
#pragma unroll
        for (int d = 0; d < 16; d++)
            w[s * 16 + d] = pack_bf2(segs[s][2*d], segs[s][2*d+1]);
    uint4* dst = reinterpret_cast<uint4*>(g_bexp + (size_t)k * ROWB);
#pragma unroll
    for (int i = 0; i < ROWW / 4; i++)
        dst[i] = make_uint4(w[4*i], w[4*i+1], w[4*i+2], w[4*i+3]);
    g_c2[k] = c2;
}

// ---- ptx helpers (all plain-sm_100 legal) ----
__device__ __forceinline__ uint32_t smem_u32(const void* p) {
    uint32_t a;
    asm("{ .reg .u64 t; cvta.to.shared.u64 t, %1; cvt.u32.u64 %0, t; }" : "=r"(a) : "l"(p));
    return a;
}
__device__ __forceinline__ void cp16(uint32_t dst, const void* src) {
    asm volatile("cp.async.cg.shared.global [%0], [%1], 16;" :: "r"(dst), "l"(src) : "memory");
}

// ---- main: mma.sync GEMM + fused argmin ----
__global__ __launch_bounds__(THREADS, 1)
void tc_label(float* __restrict__ out) {
    extern __shared__ uint8_t smem[];
    const uint32_t sb = smem_u32(smem);
    const int tid = threadIdx.x, lane = tid & 31, warp = tid >> 5;
    const int lm4 = lane & 3;
    const int pbase = blockIdx.x * 224 + warp * 16;

    // A fragments for this warp's 16 points: resident for whole kernel.
    // m16n8k16 A layout: a0=(r,k0k1) a1=(r+8,k0k1) a2=(r,k8k9) a3=(r+8,k8k9), r=lane/4, k0=(lane%4)*2
    uint32_t A[KSTEPS][4];
    {
        const uint32_t* rlo = reinterpret_cast<const uint32_t*>(g_aexp + (size_t)(pbase + (lane >> 2)) * ROWB);
        const uint32_t* rhi = reinterpret_cast<const uint32_t*>(g_aexp + (size_t)(pbase + (lane >> 2) + 8) * ROWB);
#pragma unroll
        for (int s = 0; s < KSTEPS; s++) {
            A[s][0] = rlo[s * 8 + lm4];
            A[s][1] = rhi[s * 8 + lm4];
            A[s][2] = rlo[s * 8 + 4 + lm4];
            A[s][3] = rhi[s * 8 + 4 + lm4];
        }
    }

    float b0v = 3.402823466e38f, b1v = 3.402823466e38f;
    int   b0i = 0, b1i = 0;

    // tile loader: 128 rows x 24 chunks + 32 c2 chunks = 3104 x 16B
    auto issue = [&](int t) {
        const uint32_t dstB = sb + SM_B(t & 1);
        const uint32_t dstC = sb + SM_C2(t & 1);
        const uint8_t* srcB = g_bexp + (size_t)t * TILE_N * ROWB;
        const uint8_t* srcC = reinterpret_cast<const uint8_t*>(g_c2 + t * TILE_N);
        for (int i = tid; i < 3104; i += THREADS) {
            if (i < 3072) {
                int row = i / 24, ch = i % 24;
                cp16(dstB + row * PITCH + ch * 16, srcB + row * ROWB + ch * 16);
            } else {
                int j = i - 3072;
                cp16(dstC + j * 16, srcC + j * 16);
            }
        }
        asm volatile("cp.async.commit_group;" ::: "memory");
    };

    issue(0);
    issue(1);

    for (int t = 0; t < NTILES; t++) {
        if (t < NTILES - 1) asm volatile("cp.async.wait_group 1;" ::: "memory");
        else                asm volatile("cp.async.wait_group 0;" ::: "memory");
        __syncthreads();

        const uint32_t bufB = sb + SM_B(t & 1);
        const float* c2s = reinterpret_cast<const float*>(smem + SM_C2(t & 1));
        const int kb = t * TILE_N;
        // ldmatrix row addr: threads 0-7 -> matrix0 rows (centers, k+0), 8-15 -> matrix1 (k+8)
        const uint32_t baddr0 = bufB + (uint32_t)(lane & 7) * PITCH + (uint32_t)((lane >> 3) & 1) * 16;

#pragma unroll 4
        for (int blk = 0; blk < TILE_N / 8; blk++) {
            float d0 = 0.f, d1 = 0.f, d2 = 0.f, d3 = 0.f;
            const uint32_t ba = baddr0 + (uint32_t)blk * (8 * PITCH);
#pragma unroll
            for (int s = 0; s < KSTEPS; s++) {
                uint32_t bb0, bb1;
                asm volatile("ldmatrix.sync.aligned.m8n8.x2.shared.b16 {%0,%1}, [%2];"
                             : "=r"(bb0), "=r"(bb1) : "r"(ba + s * 32));
                asm volatile("mma.sync.aligned.m16n8k16.row.col.f32.bf16.bf16.f32 "
                             "{%0,%1,%2,%3}, {%4,%5,%6,%7}, {%8,%9}, {%0,%1,%2,%3};"
                             : "+f"(d0), "+f"(d1), "+f"(d2), "+f"(d3)
                             : "r"(A[s][0]), "r"(A[s][1]), "r"(A[s][2]), "r"(A[s][3]),
                               "r"(bb0), "r"(bb1));
            }
            const int ci = blk * 8 + lm4 * 2;        // D cols (lane%4)*2, +1
            const float c2a = c2s[ci], c2b = c2s[ci + 1];
            const float v0 = fmaf(-2.0f, d0, c2a);
            const float v1 = fmaf(-2.0f, d1, c2b);
            const float v2 = fmaf(-2.0f, d2, c2a);
            const float v3 = fmaf(-2.0f, d3, c2b);
            const int idx = kb + ci;
            if (v0 < b0v) { b0v = v0; b0i = idx; }
            if (v1 < b0v) { b0v = v1; b0i = idx + 1; }
            if (v2 < b1v) { b1v = v2; b1i = idx; }
            if (v3 < b1v) { b1v = v3; b1i = idx + 1; }
        }
        __syncthreads();
        if (t + 2 < NTILES) issue(t + 2);
    }

    // reduce across the 4 threads sharing each row (ties -> lower index)
#pragma unroll
    for (int off = 1; off < 4; off <<= 1) {
        float ov = __shfl_xor_sync(0xFFFFFFFFu, b0v, off);
        int   oi = __shfl_xor_sync(0xFFFFFFFFu, b0i, off);
        if (ov < b0v || (ov == b0v && oi < b0i)) { b0v = ov; b0i = oi; }
        ov = __shfl_xor_sync(0xFFFFFFFFu, b1v, off);
        oi = __shfl_xor_sync(0xFFFFFFFFu, b1i, off);
        if (ov < b1v || (ov == b1v && oi < b1i)) { b1v = ov; b1i = oi; }
    }
    if ((lane & 3) == 0) {
        const int r = lane >> 2;
        const int p0 = pbase + r, p1 = pbase + r + 8;
        if (p0 < NPOINTS) out[p0] = (float)b0i;
        if (p1 < NPOINTS) out[p1] = (float)b1i;
    }
}

extern "C" void kernel_launch(void* const* d_in, const int* in_sizes, int n_in,
                              void* d_out, int out_size) {
    const float* x; const float* c; int nx, nc;
    if (in_sizes[0] >= in_sizes[1]) { x = (const float*)d_in[0]; nx = in_sizes[0];
                                      c = (const float*)d_in[1]; nc = in_sizes[1]; }
    else                            { x = (const float*)d_in[1]; nx = in_sizes[1];
                                      c = (const float*)d_in[0]; nc = in_sizes[0]; }
    float* out = (float*)d_out;
    int N = nx / DIMS;   // 32768
    int K = nc / DIMS;   // 8192

    prep_points <<<(N + 127) / 128, 128>>>(x, N);
    prep_centers<<<(K + 127) / 128, 128>>>(c, K);

    cudaFuncSetAttribute(tc_label, cudaFuncAttributeMaxDynamicSharedMemorySize, SMEM_TOTAL);
    tc_label<<<GRID, THREADS, SMEM_TOTAL>>>(out);
}